// round 1
// baseline (speedup 1.0000x reference)
#include <cuda_runtime.h>

#define NN 50000
#define NE 800000
#define HID 128
#define LATD 64
#define IN_NODE 11
#define IN_EDGE 4

// ---------------- device scratch (static globals: allocation-free) ----------------
__device__ float g_h0buf[NN * HID];   // ping
__device__ float g_h1buf[NN * HID];   // pong
__device__ float g_agg[NN * HID];     // scatter-sum target
__device__ float g_P1[NN * HID];      // h @ W1[0:128]
__device__ float g_P2[NN * HID];      // h @ W1[128:256]
__device__ float g_radial[NE];
__device__ float g_wsum[HID * HID];   // node W1[0:128] + W1[256:384]

__device__ __forceinline__ float elu(float v) {
    return v > 0.f ? v : (__expf(v) - 1.f);
}

__device__ __forceinline__ void red4(float* p, float a, float b, float c, float d) {
    asm volatile("red.global.add.v4.f32 [%0], {%1,%2,%3,%4};"
                 :: "l"(p), "f"(a), "f"(b), "f"(c), "f"(d) : "memory");
}

// ---------------- small kernels ----------------
__global__ void embed_kernel(const float* __restrict__ h0,
                             const float* __restrict__ emb_w,
                             const float* __restrict__ emb_b) {
    int idx = blockIdx.x * 256 + threadIdx.x;
    if (idx >= NN * HID) return;
    int n = idx >> 7, j = idx & 127;
    float acc = emb_b[j];
#pragma unroll
    for (int k = 0; k < IN_NODE; k++)
        acc += h0[n * IN_NODE + k] * emb_w[k * HID + j];
    g_h0buf[idx] = acc;
}

__global__ void radial_kernel(const float* __restrict__ x,
                              const int* __restrict__ row,
                              const int* __restrict__ col) {
    int e = blockIdx.x * 256 + threadIdx.x;
    if (e >= NE) return;
    int r = row[e], c = col[e];
    float dx = x[r * 3 + 0] - x[c * 3 + 0];
    float dy = x[r * 3 + 1] - x[c * 3 + 1];
    float dz = x[r * 3 + 2] - x[c * 3 + 2];
    g_radial[e] = dx * dx + dy * dy + dz * dz;
}

__global__ void zero_agg_kernel() {
    int i = blockIdx.x * 256 + threadIdx.x;
    if (i < NN * HID) g_agg[i] = 0.f;
}

__global__ void wsum_kernel(const float* __restrict__ nw1, int layer) {
    int i = blockIdx.x * 256 + threadIdx.x;
    if (i >= HID * HID) return;
    int k = i >> 7, j = i & 127;
    const float* base = nw1 + layer * (3 * HID) * HID;
    g_wsum[i] = base[k * HID + j] + base[(2 * HID + k) * HID + j];
}

// ---------------- P1/P2 precompute: [N,128] @ [128,128] ----------------
__global__ void __launch_bounds__(256, 2)
pre_kernel(const float* __restrict__ ew1, int layer) {
    __shared__ float As[32 * 132];
    __shared__ float Bs[32 * 132];
    const float* src = (layer == 0) ? g_h0buf : g_h1buf;
    const float* W = ew1 + (layer * 261 + blockIdx.y * HID) * HID;
    float* P = blockIdx.y ? g_P2 : g_P1;

    int tid = threadIdx.x;
    int tx = tid & 15, ty = tid >> 4;
    int n0 = blockIdx.x * 128;

    float acc[8][8];
#pragma unroll
    for (int i = 0; i < 8; i++)
#pragma unroll
        for (int j = 0; j < 8; j++) acc[i][j] = 0.f;

    for (int k0 = 0; k0 < HID; k0 += 32) {
#pragma unroll
        for (int it = 0; it < 4; it++) {
            int s = tid + it * 256;
            int e = s >> 3, kq = s & 7;
            int n = n0 + e;
            float4 v = make_float4(0.f, 0.f, 0.f, 0.f);
            if (n < NN) v = *(const float4*)(src + n * HID + k0 + kq * 4);
            As[(kq * 4 + 0) * 132 + e] = v.x;
            As[(kq * 4 + 1) * 132 + e] = v.y;
            As[(kq * 4 + 2) * 132 + e] = v.z;
            As[(kq * 4 + 3) * 132 + e] = v.w;
        }
#pragma unroll
        for (int it = 0; it < 4; it++) {
            int s = tid + it * 256;
            int kk = s >> 5, jq = s & 31;
            *(float4*)(Bs + kk * 132 + jq * 4) =
                *(const float4*)(W + (k0 + kk) * HID + jq * 4);
        }
        __syncthreads();
#pragma unroll
        for (int kk = 0; kk < 32; kk++) {
            float4 a0 = *(const float4*)(As + kk * 132 + ty * 8);
            float4 a1 = *(const float4*)(As + kk * 132 + ty * 8 + 4);
            float4 b0 = *(const float4*)(Bs + kk * 132 + tx * 8);
            float4 b1 = *(const float4*)(Bs + kk * 132 + tx * 8 + 4);
            float a[8] = {a0.x, a0.y, a0.z, a0.w, a1.x, a1.y, a1.z, a1.w};
            float b[8] = {b0.x, b0.y, b0.z, b0.w, b1.x, b1.y, b1.z, b1.w};
#pragma unroll
            for (int i = 0; i < 8; i++)
#pragma unroll
                for (int j = 0; j < 8; j++) acc[i][j] += a[i] * b[j];
        }
        __syncthreads();
    }
#pragma unroll
    for (int i = 0; i < 8; i++) {
        int n = n0 + ty * 8 + i;
        if (n < NN) {
#pragma unroll
            for (int j = 0; j < 8; j += 4) {
                float4 v = make_float4(acc[i][j], acc[i][j + 1], acc[i][j + 2], acc[i][j + 3]);
                *(float4*)(P + n * HID + tx * 8 + j) = v;
            }
        }
    }
}

// ---------------- edge kernel: gather-add + ELU + [128x128x128] GEMM + scatter ----------------
__global__ void __launch_bounds__(256, 2)
edge_kernel(const float* __restrict__ edge_attr,
            const float* __restrict__ ew1, const float* __restrict__ eb1,
            const float* __restrict__ ew2, const float* __restrict__ eb2,
            const int* __restrict__ row, const int* __restrict__ col, int layer) {
    extern __shared__ float esm[];
    float* Ts = esm;              // [128][132]
    float* Bs = esm + 128 * 132;  // [32][132]

    int tid = threadIdx.x;
    int tx = tid & 15, ty = tid >> 4;
    int e0 = blockIdx.x * 128;

    const float* Wtail = ew1 + (layer * 261 + 2 * HID) * HID;  // rows 256..260
    const float* b1 = eb1 + layer * HID;

    // hoisted tail weights + bias (column-slice of this thread)
    float4 wr[2], wA[2], wB[2], wC[2], wD[2], bb[2];
#pragma unroll
    for (int q = 0; q < 2; q++) {
        int jb = tx * 8 + q * 4;
        wr[q] = *(const float4*)(Wtail + 0 * HID + jb);
        wA[q] = *(const float4*)(Wtail + 1 * HID + jb);
        wB[q] = *(const float4*)(Wtail + 2 * HID + jb);
        wC[q] = *(const float4*)(Wtail + 3 * HID + jb);
        wD[q] = *(const float4*)(Wtail + 4 * HID + jb);
        bb[q] = *(const float4*)(b1 + jb);
    }

    // build Ts = elu(P1[row] + P2[col] + radial*wr + ea@Wtail + b1)
#pragma unroll
    for (int i = 0; i < 8; i++) {
        int e = e0 + ty * 8 + i;
        int r = row[e], c = col[e];
        float rad = g_radial[e];
        float4 ea = *(const float4*)(edge_attr + e * 4);
#pragma unroll
        for (int q = 0; q < 2; q++) {
            int jb = tx * 8 + q * 4;
            float4 p1 = *(const float4*)(g_P1 + r * HID + jb);
            float4 p2 = *(const float4*)(g_P2 + c * HID + jb);
            float o0 = p1.x + p2.x + rad * wr[q].x + ea.x * wA[q].x + ea.y * wB[q].x + ea.z * wC[q].x + ea.w * wD[q].x + bb[q].x;
            float o1 = p1.y + p2.y + rad * wr[q].y + ea.x * wA[q].y + ea.y * wB[q].y + ea.z * wC[q].y + ea.w * wD[q].y + bb[q].y;
            float o2 = p1.z + p2.z + rad * wr[q].z + ea.x * wA[q].z + ea.y * wB[q].z + ea.z * wC[q].z + ea.w * wD[q].z + bb[q].z;
            float o3 = p1.w + p2.w + rad * wr[q].w + ea.x * wA[q].w + ea.y * wB[q].w + ea.z * wC[q].w + ea.w * wD[q].w + bb[q].w;
            float* trow = Ts + (ty * 8 + i) * 132 + jb;
            trow[0] = elu(o0); trow[1] = elu(o1); trow[2] = elu(o2); trow[3] = elu(o3);
        }
    }

    // GEMM2: m = elu(Ts @ W2 + b2), scatter-add to agg[row]
    float acc[8][8];
#pragma unroll
    for (int i = 0; i < 8; i++)
#pragma unroll
        for (int j = 0; j < 8; j++) acc[i][j] = 0.f;

    const float* W2 = ew2 + layer * HID * HID;
    for (int k0 = 0; k0 < HID; k0 += 32) {
#pragma unroll
        for (int it = 0; it < 4; it++) {
            int s = tid + it * 256;
            int kk = s >> 5, jq = s & 31;
            *(float4*)(Bs + kk * 132 + jq * 4) =
                *(const float4*)(W2 + (k0 + kk) * HID + jq * 4);
        }
        __syncthreads();
#pragma unroll
        for (int kk = 0; kk < 32; kk++) {
            float a[8];
#pragma unroll
            for (int i = 0; i < 8; i++) a[i] = Ts[(ty * 8 + i) * 132 + k0 + kk];
            float4 b0 = *(const float4*)(Bs + kk * 132 + tx * 8);
            float4 b4 = *(const float4*)(Bs + kk * 132 + tx * 8 + 4);
            float b[8] = {b0.x, b0.y, b0.z, b0.w, b4.x, b4.y, b4.z, b4.w};
#pragma unroll
            for (int i = 0; i < 8; i++)
#pragma unroll
                for (int j = 0; j < 8; j++) acc[i][j] += a[i] * b[j];
        }
        __syncthreads();
    }

    const float* b2 = eb2 + layer * HID;
    float bj[8];
#pragma unroll
    for (int j = 0; j < 8; j++) bj[j] = b2[tx * 8 + j];
#pragma unroll
    for (int i = 0; i < 8; i++) {
        int e = e0 + ty * 8 + i;
        int r = row[e];
        float v[8];
#pragma unroll
        for (int j = 0; j < 8; j++) v[j] = elu(acc[i][j] + bj[j]);
        float* dst = g_agg + r * HID + tx * 8;
        red4(dst, v[0], v[1], v[2], v[3]);
        red4(dst + 4, v[4], v[5], v[6], v[7]);
    }
}

// ---------------- node kernel: [N, h|agg] MLP -> new h ----------------
__global__ void __launch_bounds__(256, 2)
node_kernel(const float* __restrict__ nw1, const float* __restrict__ nb1,
            const float* __restrict__ nw2, const float* __restrict__ nb2, int layer) {
    extern __shared__ float sm[];
    float* Ts = sm;               // [128][132]
    float* As = sm + 128 * 132;   // [32][132]
    float* Bs = As + 32 * 132;    // [32][132]

    const float* hsrc = (layer == 0) ? g_h0buf : g_h1buf;
    float* hdst = (layer == 0) ? g_h1buf : g_h0buf;

    int tid = threadIdx.x;
    int tx = tid & 15, ty = tid >> 4;
    int n0 = blockIdx.x * 128;

    float acc[8][8];
#pragma unroll
    for (int i = 0; i < 8; i++)
#pragma unroll
        for (int j = 0; j < 8; j++) acc[i][j] = 0.f;

    // GEMM1: K = 256 (h-part uses wsum = W1a + W1c; agg-part uses W1b)
    for (int k0 = 0; k0 < 2 * HID; k0 += 32) {
        const float* Asrc = (k0 < HID) ? (hsrc + k0) : (g_agg + (k0 - HID));
        const float* Bsrc = (k0 < HID) ? (g_wsum + k0 * HID)
                                       : (nw1 + (layer * 3 * HID + HID + (k0 - HID)) * HID);
#pragma unroll
        for (int it = 0; it < 4; it++) {
            int s = tid + it * 256;
            int e = s >> 3, kq = s & 7;
            int n = n0 + e;
            float4 v = make_float4(0.f, 0.f, 0.f, 0.f);
            if (n < NN) v = *(const float4*)(Asrc + n * HID + kq * 4);
            As[(kq * 4 + 0) * 132 + e] = v.x;
            As[(kq * 4 + 1) * 132 + e] = v.y;
            As[(kq * 4 + 2) * 132 + e] = v.z;
            As[(kq * 4 + 3) * 132 + e] = v.w;
        }
#pragma unroll
        for (int it = 0; it < 4; it++) {
            int s = tid + it * 256;
            int kk = s >> 5, jq = s & 31;
            *(float4*)(Bs + kk * 132 + jq * 4) =
                *(const float4*)(Bsrc + kk * HID + jq * 4);
        }
        __syncthreads();
#pragma unroll
        for (int kk = 0; kk < 32; kk++) {
            float4 a0 = *(const float4*)(As + kk * 132 + ty * 8);
            float4 a1 = *(const float4*)(As + kk * 132 + ty * 8 + 4);
            float4 b0 = *(const float4*)(Bs + kk * 132 + tx * 8);
            float4 b4 = *(const float4*)(Bs + kk * 132 + tx * 8 + 4);
            float a[8] = {a0.x, a0.y, a0.z, a0.w, a1.x, a1.y, a1.z, a1.w};
            float b[8] = {b0.x, b0.y, b0.z, b0.w, b4.x, b4.y, b4.z, b4.w};
#pragma unroll
            for (int i = 0; i < 8; i++)
#pragma unroll
                for (int j = 0; j < 8; j++) acc[i][j] += a[i] * b[j];
        }
        __syncthreads();
    }

    const float* b1 = nb1 + layer * HID;
#pragma unroll
    for (int i = 0; i < 8; i++)
#pragma unroll
        for (int j = 0; j < 8; j++)
            Ts[(ty * 8 + i) * 132 + tx * 8 + j] = elu(acc[i][j] + b1[tx * 8 + j]);

    // GEMM2: K = 128 (no ELU on output)
#pragma unroll
    for (int i = 0; i < 8; i++)
#pragma unroll
        for (int j = 0; j < 8; j++) acc[i][j] = 0.f;

    const float* W2 = nw2 + layer * HID * HID;
    for (int k0 = 0; k0 < HID; k0 += 32) {
#pragma unroll
        for (int it = 0; it < 4; it++) {
            int s = tid + it * 256;
            int kk = s >> 5, jq = s & 31;
            *(float4*)(Bs + kk * 132 + jq * 4) =
                *(const float4*)(W2 + (k0 + kk) * HID + jq * 4);
        }
        __syncthreads();
#pragma unroll
        for (int kk = 0; kk < 32; kk++) {
            float a[8];
#pragma unroll
            for (int i = 0; i < 8; i++) a[i] = Ts[(ty * 8 + i) * 132 + k0 + kk];
            float4 b0 = *(const float4*)(Bs + kk * 132 + tx * 8);
            float4 b4 = *(const float4*)(Bs + kk * 132 + tx * 8 + 4);
            float b[8] = {b0.x, b0.y, b0.z, b0.w, b4.x, b4.y, b4.z, b4.w};
#pragma unroll
            for (int i = 0; i < 8; i++)
#pragma unroll
                for (int j = 0; j < 8; j++) acc[i][j] += a[i] * b[j];
        }
        __syncthreads();
    }

    const float* b2 = nb2 + layer * HID;
#pragma unroll
    for (int i = 0; i < 8; i++) {
        int n = n0 + ty * 8 + i;
        if (n < NN) {
#pragma unroll
            for (int j = 0; j < 8; j++)
                hdst[n * HID + tx * 8 + j] = acc[i][j] + b2[tx * 8 + j];
        }
    }
}

// ---------------- final: mu/var heads + reparameterize ----------------
__global__ void final_kernel(const float* __restrict__ label,
                             const float* __restrict__ eps,
                             const float* __restrict__ mu_w, const float* __restrict__ mu_b,
                             const float* __restrict__ var_w, const float* __restrict__ var_b,
                             float* __restrict__ out) {
    int idx = blockIdx.x * 256 + threadIdx.x;
    if (idx >= NN * LATD) return;
    int n = idx >> 6, l = idx & 63;
    float am = mu_b[l], av = var_b[l];
    const float* hrow = g_h0buf + n * HID;  // after layer 1, h lives in g_h0buf
#pragma unroll 4
    for (int k = 0; k < HID; k++) {
        float hv = hrow[k];
        am += hv * mu_w[k * LATD + l];
        av += hv * var_w[k * LATD + l];
    }
#pragma unroll
    for (int c = 0; c < 7; c++) {
        float lv = label[n * 7 + c];
        am += lv * mu_w[(HID + c) * LATD + l];
        av += lv * var_w[(HID + c) * LATD + l];
    }
    out[idx] = am + 0.01f * eps[idx] * __expf(0.5f * av);
}

// ---------------- launch ----------------
extern "C" void kernel_launch(void* const* d_in, const int* in_sizes, int n_in,
                              void* d_out, int out_size) {
    const float* h0        = (const float*)d_in[0];
    const float* label     = (const float*)d_in[1];
    const float* x         = (const float*)d_in[2];
    const float* edge_attr = (const float*)d_in[3];
    const float* eps       = (const float*)d_in[4];
    const float* emb_w     = (const float*)d_in[5];
    const float* emb_b     = (const float*)d_in[6];
    const float* ew1       = (const float*)d_in[7];
    const float* eb1       = (const float*)d_in[8];
    const float* ew2       = (const float*)d_in[9];
    const float* eb2       = (const float*)d_in[10];
    const float* nw1       = (const float*)d_in[11];
    const float* nb1       = (const float*)d_in[12];
    const float* nw2       = (const float*)d_in[13];
    const float* nb2       = (const float*)d_in[14];
    const float* mu_w      = (const float*)d_in[15];
    const float* mu_b      = (const float*)d_in[16];
    const float* var_w     = (const float*)d_in[17];
    const float* var_b     = (const float*)d_in[18];
    const int*   edges     = (const int*)d_in[19];
    const int* rowp = edges;
    const int* colp = edges + NE;
    float* out = (float*)d_out;

    const int EDGE_SMEM = (128 * 132 + 32 * 132) * 4;              // 84480
    const int NODE_SMEM = (128 * 132 + 32 * 132 + 32 * 132) * 4;   // 101376
    cudaFuncSetAttribute(edge_kernel, cudaFuncAttributeMaxDynamicSharedMemorySize, EDGE_SMEM);
    cudaFuncSetAttribute(node_kernel, cudaFuncAttributeMaxDynamicSharedMemorySize, NODE_SMEM);

    embed_kernel<<<(NN * HID + 255) / 256, 256>>>(h0, emb_w, emb_b);
    radial_kernel<<<(NE + 255) / 256, 256>>>(x, rowp, colp);

    for (int layer = 0; layer < 2; layer++) {
        zero_agg_kernel<<<(NN * HID + 255) / 256, 256>>>();
        pre_kernel<<<dim3((NN + 127) / 128, 2), 256>>>(ew1, layer);
        wsum_kernel<<<(HID * HID + 255) / 256, 256>>>(nw1, layer);
        edge_kernel<<<NE / 128, 256, EDGE_SMEM>>>(edge_attr, ew1, eb1, ew2, eb2,
                                                  rowp, colp, layer);
        node_kernel<<<(NN + 127) / 128, 256, NODE_SMEM>>>(nw1, nb1, nw2, nb2, layer);
    }

    final_kernel<<<(NN * LATD + 255) / 256, 256>>>(label, eps, mu_w, mu_b,
                                                   var_w, var_b, out);
}